// round 17
// baseline (speedup 1.0000x reference)
#include <cuda_runtime.h>
#include <cuda_fp16.h>
#include <cstdint>

#define DHID   512
#define KC     512
#define BM     64          // rows per CTA
#define BK     32          // K elems per chunk = 64 bytes fp16
#define NCH    (DHID/BK)   // 16 chunks
#define NT     512         // 16 warps, each owns 64x32 output tile

#define A_STAGE (BM * 64)              // 4 KB
#define B_STAGE (KC * 64)              // 32 KB
#define DYN_SMEM (2*(A_STAGE + B_STAGE) + 1024)   // 72 KB + slack (2 CTAs/SM)

__device__ __half g_wh[KC * DHID];   // centers fp16, [n][k] row-major
__device__ float  g_c2[KC];

// ---------------------------------------------------------------------------
__device__ __forceinline__ uint32_t smem_u32(const void* p) {
    uint32_t a;
    asm("{ .reg .u64 t; cvta.to.shared.u64 t, %1; cvt.u32.u64 %0, t; }" : "=r"(a) : "l"(p));
    return a;
}
__device__ __forceinline__ uint32_t pack_f16(float lo, float hi) {
    uint32_t r;
    asm("cvt.rn.f16x2.f32 %0, %1, %2;" : "=r"(r) : "f"(hi), "f"(lo));
    return r;
}
__device__ __forceinline__ float2 unpack_f16(uint32_t u) {
    __half2 h = *reinterpret_cast<__half2*>(&u);
    return __half22float2(h);
}
// 64-byte-row swizzle (SW64): bits[4:5] ^= bits[7:8]
#define SWZ64(o) ((o) ^ (((o) >> 3) & 0x30))

__device__ __forceinline__ void cp_async16(uint32_t dst, const void* src) {
    asm volatile("cp.async.cg.shared.global [%0], [%1], 16;\n" :: "r"(dst), "l"(src) : "memory");
}
#define CP_COMMIT() asm volatile("cp.async.commit_group;\n" ::: "memory")
#define CP_WAIT0()  asm volatile("cp.async.wait_group 0;\n" ::: "memory")

#define LDSM4(r, a) \
    asm volatile("ldmatrix.sync.aligned.m8n8.x4.shared.b16 {%0,%1,%2,%3}, [%4];" \
                 : "=r"((r)[0]), "=r"((r)[1]), "=r"((r)[2]), "=r"((r)[3]) : "r"(a))

// fp16 inputs, fp16 accumulators
#define MMAF16(d, a, b0, b1) \
    asm volatile("mma.sync.aligned.m16n8k16.row.col.f16.f16.f16.f16 " \
                 "{%0,%1}, {%2,%3,%4,%5}, {%6,%7}, {%0,%1};" \
                 : "+r"((d)[0]), "+r"((d)[1]) \
                 : "r"((a)[0]), "r"((a)[1]), "r"((a)[2]), "r"((a)[3]), \
                   "r"(b0), "r"(b1))

// ---------------------------------------------------------------------------
// Prep W: centers fp32 -> fp16 + ||c||^2. One block per cluster row.
// ---------------------------------------------------------------------------
__global__ void prep_w_kernel(const float* __restrict__ centers) {
    const int c = blockIdx.x, t = threadIdx.x;       // 256 threads
    const float2* row = reinterpret_cast<const float2*>(centers + (size_t)c * DHID);
    float2 v = row[t];
    reinterpret_cast<uint32_t*>(g_wh + (size_t)c * DHID)[t] = pack_f16(v.x, v.y);
    float s = v.x * v.x + v.y * v.y;
    #pragma unroll
    for (int o = 16; o > 0; o >>= 1) s += __shfl_xor_sync(0xffffffffu, s, o);
    __shared__ float ws[8];
    if ((t & 31) == 0) ws[t >> 5] = s;
    __syncthreads();
    if (t == 0) {
        float tot = 0.f;
        #pragma unroll
        for (int i = 0; i < 8; i++) tot += ws[i];
        g_c2[c] = tot;
    }
}

// ---------------------------------------------------------------------------
// Main fused kernel: 64 rows x 512 clusters per CTA, 2 CTAs/SM.
// 16 warps, each owns a 64x32 tile (warp wid covers cols wid*32..wid*32+31).
// ---------------------------------------------------------------------------
extern __shared__ char dynsmem[];

__global__ __launch_bounds__(NT, 2)
void qsoft_mma_kernel(const float* __restrict__ x, float* __restrict__ out) {
    __shared__ float xs_sm[BM];
    __shared__ float c2s[KC];
    __shared__ float rs_sm[BM][16];
    __shared__ float inv_sm[BM];

    const int tid  = threadIdx.x;
    const int wid  = tid >> 5;
    const int lane = tid & 31;
    const int rowBase = blockIdx.x * BM;

    const uint32_t sbase = (smem_u32(dynsmem) + 1023u) & ~1023u;
    const uint32_t Abuf[2] = { sbase,              sbase + A_STAGE };
    const uint32_t Bbuf[2] = { sbase + 2*A_STAGE,  sbase + 2*A_STAGE + B_STAGE };

    // ---- A mapping: row = tid/8 (0..63), 4 floats at col (tid%8)*4 ----
    const int arow = tid >> 3;
    const int asub = tid & 7;

    // ldmatrix lane addressing (within-tile offsets)
    const int a_r  = ((lane >> 3) & 1) * 8 + (lane & 7);   // A row in m16
    const int a_kb = ((lane >> 4) & 1) * 16;               // A k-byte
    const int b_r  = ((lane >> 4) & 1) * 8 + (lane & 7);   // B row in n16
    const int b_kb = ((lane >> 3) & 1) * 16;               // B k-byte

    uint32_t acc[4][4][2];
    #pragma unroll
    for (int mi = 0; mi < 4; mi++)
        #pragma unroll
        for (int ni = 0; ni < 4; ni++) { acc[mi][ni][0] = 0u; acc[mi][ni][1] = 0u; }

    float sq = 0.f;
    float4 f;

    // ---------------- loaders ----------------
    auto lda = [&](int c) {
        f = *reinterpret_cast<const float4*>(
            x + (size_t)(rowBase + arow) * DHID + c * BK + asub * 4);
    };
    auto sta = [&](int s) {
        sq += f.x*f.x + f.y*f.y + f.z*f.z + f.w*f.w;
        uint32_t p0 = pack_f16(f.x, f.y);
        uint32_t p1 = pack_f16(f.z, f.w);
        uint32_t off = (uint32_t)arow * 64u + (uint32_t)asub * 8u;
        asm volatile("st.shared.v2.b32 [%0], {%1,%2};"
                     :: "r"(Abuf[s] + SWZ64(off)), "r"(p0), "r"(p1) : "memory");
    };
    auto ldb = [&](int c, int s) {
        #pragma unroll
        for (int k = 0; k < 4; k++) {
            int idx = tid + k * NT;          // 0..2047 (16B chunks)
            int n = idx >> 2, i = idx & 3;
            const char* src = reinterpret_cast<const char*>(g_wh)
                            + (size_t)n * (DHID * 2) + c * 64 + i * 16;
            uint32_t off = (uint32_t)n * 64u + (uint32_t)i * 16u;
            cp_async16(Bbuf[s] + SWZ64(off), src);
        }
    };

    // ---------------- compute one K-chunk (warp: 64 rows x 32 cols) ---------
    auto compute = [&](int s) {
        const uint32_t Ab = Abuf[s], Bb = Bbuf[s];
        #pragma unroll
        for (int ks = 0; ks < 2; ks++) {
            uint32_t b[2][4];
            #pragma unroll
            for (int j = 0; j < 2; j++) {
                uint32_t off = (uint32_t)(wid * 32 + j * 16 + b_r) * 64u
                             + (uint32_t)(ks * 32 + b_kb);
                LDSM4(b[j], Bb + SWZ64(off));
            }
            #pragma unroll
            for (int mi = 0; mi < 4; mi++) {
                uint32_t a[4];
                uint32_t off = (uint32_t)(mi * 16 + a_r) * 64u
                             + (uint32_t)(ks * 32 + a_kb);
                LDSM4(a, Ab + SWZ64(off));
                MMAF16(acc[mi][0], a, b[0][0], b[0][1]);
                MMAF16(acc[mi][1], a, b[0][2], b[0][3]);
                MMAF16(acc[mi][2], a, b[1][0], b[1][1]);
                MMAF16(acc[mi][3], a, b[1][2], b[1][3]);
            }
        }
    };

    // ---------------- pipeline (2-stage double buffer) ----------------
    lda(0);
    ldb(0, 0); CP_COMMIT();
    sta(0);
    CP_WAIT0(); __syncthreads();

    for (int c = 0; c < NCH; c++) {
        const int s = c & 1;
        if (c + 1 < NCH) { lda(c + 1); ldb(c + 1, s ^ 1); CP_COMMIT(); }
        compute(s);
        if (c + 1 < NCH) { sta(s ^ 1); CP_WAIT0(); }
        __syncthreads();
    }

    // ---------------- epilogue ----------------
    // ||x||^2: 8 consecutive lanes own one row -> xor 1,2,4
    sq += __shfl_xor_sync(0xffffffffu, sq, 1);
    sq += __shfl_xor_sync(0xffffffffu, sq, 2);
    sq += __shfl_xor_sync(0xffffffffu, sq, 4);
    if ((tid & 7) == 0) xs_sm[arow] = sq;
    for (int i = tid; i < KC; i += NT) c2s[i] = g_c2[i];
    __syncthreads();

    const int qrow = lane >> 2;                        // 0..7
    const int wcol = wid * 32 + (lane & 3) * 2;

    // pass 1: row sums of q (each warp covers 32 cols; combine over 16 warps)
    #pragma unroll
    for (int mi = 0; mi < 4; mi++) {
        const int r0 = mi * 16 + qrow, r1 = r0 + 8;
        const float x20 = xs_sm[r0], x21 = xs_sm[r1];
        float s0 = 0.f, s1 = 0.f;
        #pragma unroll
        for (int ni = 0; ni < 4; ni++) {
            const float cc0 = c2s[wcol + ni * 8];
            const float cc1 = c2s[wcol + ni * 8 + 1];
            float2 v0 = unpack_f16(acc[mi][ni][0]);
            float2 v1 = unpack_f16(acc[mi][ni][1]);
            s0 += __fdividef(1.f, 1.f + fmaxf(fmaf(-2.f, v0.x, x20 + cc0), 0.f))
                + __fdividef(1.f, 1.f + fmaxf(fmaf(-2.f, v0.y, x20 + cc1), 0.f));
            s1 += __fdividef(1.f, 1.f + fmaxf(fmaf(-2.f, v1.x, x21 + cc0), 0.f))
                + __fdividef(1.f, 1.f + fmaxf(fmaf(-2.f, v1.y, x21 + cc1), 0.f));
        }
        s0 += __shfl_xor_sync(0xffffffffu, s0, 1);
        s0 += __shfl_xor_sync(0xffffffffu, s0, 2);
        s1 += __shfl_xor_sync(0xffffffffu, s1, 1);
        s1 += __shfl_xor_sync(0xffffffffu, s1, 2);
        if ((lane & 3) == 0) { rs_sm[r0][wid] = s0; rs_sm[r1][wid] = s1; }
    }
    __syncthreads();
    if (tid < BM) {
        float t = 0.f;
        #pragma unroll
        for (int w = 0; w < 16; w++) t += rs_sm[tid][w];
        inv_sm[tid] = __fdividef(1.f, t);
    }
    __syncthreads();

    // pass 2: recompute q, scale, store
    #pragma unroll
    for (int mi = 0; mi < 4; mi++) {
        const int r0 = mi * 16 + qrow, r1 = r0 + 8;
        const float x20 = xs_sm[r0], x21 = xs_sm[r1];
        const float inv0 = inv_sm[r0], inv1 = inv_sm[r1];
        float* o0 = out + (size_t)(rowBase + r0) * KC + wcol;
        float* o1 = out + (size_t)(rowBase + r1) * KC + wcol;
        #pragma unroll
        for (int ni = 0; ni < 4; ni++) {
            const float cc0 = c2s[wcol + ni * 8];
            const float cc1 = c2s[wcol + ni * 8 + 1];
            float2 v0 = unpack_f16(acc[mi][ni][0]);
            float2 v1 = unpack_f16(acc[mi][ni][1]);
            float q00 = __fdividef(inv0, 1.f + fmaxf(fmaf(-2.f, v0.x, x20 + cc0), 0.f));
            float q01 = __fdividef(inv0, 1.f + fmaxf(fmaf(-2.f, v0.y, x20 + cc1), 0.f));
            float q10 = __fdividef(inv1, 1.f + fmaxf(fmaf(-2.f, v1.x, x21 + cc0), 0.f));
            float q11 = __fdividef(inv1, 1.f + fmaxf(fmaf(-2.f, v1.y, x21 + cc1), 0.f));
            *reinterpret_cast<float2*>(o0 + ni * 8) = make_float2(q00, q01);
            *reinterpret_cast<float2*>(o1 + ni * 8) = make_float2(q10, q11);
        }
    }
}

// ---------------------------------------------------------------------------
extern "C" void kernel_launch(void* const* d_in, const int* in_sizes, int n_in,
                              void* d_out, int out_size) {
    const float* x       = (const float*)d_in[0];
    const float* centers = (const float*)d_in[1];
    float*       out     = (float*)d_out;
    const int N = in_sizes[0] / DHID;   // 131072

    cudaFuncSetAttribute(qsoft_mma_kernel,
                         cudaFuncAttributeMaxDynamicSharedMemorySize, DYN_SMEM);

    prep_w_kernel<<<KC, 256>>>(centers);
    qsoft_mma_kernel<<<N / BM, NT, DYN_SMEM>>>(x, out);
}